// round 1
// baseline (speedup 1.0000x reference)
#include <cuda_runtime.h>
#include <math.h>

// Problem constants (shapes fixed by the dataset: x[4,4096,4096], W[64,4096], b[64])
#define HDIM 4096
#define EXP  64
#define KC   32      // K chunk per smem stage
#define MT   128     // rows per CTA
#define TOPK 8

// ---------------------------------------------------------------------------
// GEMM: logits[M, 64] = x[M, 4096] @ W[64, 4096]^T + b
// Register blocking: each thread owns 8 rows x 8 experts (as 4 expert-pairs in
// packed f32x2 accumulators). 128 threads/CTA -> 128 rows x 64 experts.
// Uses Blackwell packed fma.rn.f32x2 to double fp32 FMA throughput.
// ---------------------------------------------------------------------------
__global__ __launch_bounds__(128, 1)
void gating_gemm_kernel(const float* __restrict__ x,
                        const float* __restrict__ W,
                        const float* __restrict__ b,
                        float* __restrict__ gate,
                        int M)
{
    __shared__ float xs[KC][MT + 1];   // [k][row], stride 129 -> conflict-free stores
    __shared__ float ws[KC][EXP + 2];  // [k][e],   stride 66 (even: keeps 8B align)

    const int tid = threadIdx.x;
    const int blk = blockIdx.x;
    const int eg  = tid & 7;    // expert group: experts eg*8 .. eg*8+7
    const int rg  = tid >> 3;   // row group:    rows    rg*8 .. rg*8+7 (0..15)

    unsigned long long acc[8][4];  // [row][expert-pair], packed f32x2
#pragma unroll
    for (int r = 0; r < 8; ++r)
#pragma unroll
        for (int q = 0; q < 4; ++q) acc[r][q] = 0ull;

    const float4* __restrict__ x4 = reinterpret_cast<const float4*>(x);
    const float4* __restrict__ w4 = reinterpret_cast<const float4*>(W);
    const long long row_base = (long long)blk * MT;

    for (int kt = 0; kt < HDIM / KC; ++kt) {
        __syncthreads();  // previous compute done before overwriting smem

        // --- stage x tile [128 rows x 32 k] transposed into xs[k][row] ---
#pragma unroll
        for (int i = 0; i < 8; ++i) {
            int f   = i * 128 + tid;      // float4 index 0..1023
            int row = f >> 3;             // 8 float4 per row-chunk
            int c4  = f & 7;
            float4 v = x4[(row_base + row) * (HDIM / 4) + (long long)kt * (KC / 4) + c4];
            int kk = c4 * 4;
            xs[kk + 0][row] = v.x;
            xs[kk + 1][row] = v.y;
            xs[kk + 2][row] = v.z;
            xs[kk + 3][row] = v.w;
        }
        // --- stage W tile [64 experts x 32 k] transposed into ws[k][e] ---
#pragma unroll
        for (int i = 0; i < 4; ++i) {
            int f  = i * 128 + tid;       // float4 index 0..511
            int e  = f >> 3;
            int c4 = f & 7;
            float4 v = w4[(long long)e * (HDIM / 4) + (long long)kt * (KC / 4) + c4];
            int kk = c4 * 4;
            ws[kk + 0][e] = v.x;
            ws[kk + 1][e] = v.y;
            ws[kk + 2][e] = v.z;
            ws[kk + 3][e] = v.w;
        }
        __syncthreads();

        // --- outer-product compute: 32 k-steps, 32 FFMA2 per thread per step ---
#pragma unroll 8
        for (int k = 0; k < KC; ++k) {
            // 4 expert-pairs directly as 8-byte loads (consecutive experts)
            unsigned long long wp[4];
            const float* wrow = &ws[k][eg * 8];
#pragma unroll
            for (int q = 0; q < 4; ++q)
                wp[q] = *reinterpret_cast<const unsigned long long*>(wrow + 2 * q);

            // 8 row values, duplicated into (x,x) packs
            unsigned long long xd[8];
            const float* xrow = &xs[k][rg * 8];
#pragma unroll
            for (int j = 0; j < 8; ++j) {
                unsigned int xb = __float_as_uint(xrow[j]);
                asm("mov.b64 %0, {%1, %1};" : "=l"(xd[j]) : "r"(xb));
            }
#pragma unroll
            for (int r = 0; r < 8; ++r)
#pragma unroll
                for (int q = 0; q < 4; ++q)
                    asm("fma.rn.f32x2 %0, %1, %2, %0;"
                        : "+l"(acc[r][q]) : "l"(xd[r]), "l"(wp[q]));
        }
    }

    // --- epilogue: unpack, add bias, write logits (== gate_logit output) ---
    float b0[4], b1[4];
#pragma unroll
    for (int q = 0; q < 4; ++q) {
        b0[q] = b[eg * 8 + 2 * q];
        b1[q] = b[eg * 8 + 2 * q + 1];
    }
#pragma unroll
    for (int r = 0; r < 8; ++r) {
        long long row = row_base + rg * 8 + r;
#pragma unroll
        for (int q = 0; q < 4; ++q) {
            unsigned int lo, hi;
            asm("mov.b64 {%0, %1}, %2;" : "=r"(lo), "=r"(hi) : "l"(acc[r][q]));
            float2 o;
            o.x = __uint_as_float(lo) + b0[q];
            o.y = __uint_as_float(hi) + b1[q];
            *reinterpret_cast<float2*>(&gate[row * EXP + eg * 8 + 2 * q]) = o;
        }
    }
}

// ---------------------------------------------------------------------------
// Top-8 + masked softmax. One warp per row. Iterative warp argmax with
// tie-break to the LOWER index (matches jax.lax.top_k stable ordering).
// ---------------------------------------------------------------------------
__global__ void gating_topk_kernel(const float* __restrict__ gate,
                                   float* __restrict__ sparse,
                                   float* __restrict__ idxf,
                                   int M)
{
    int gtid = blockIdx.x * blockDim.x + threadIdx.x;
    int row  = gtid >> 5;
    int lane = gtid & 31;
    if (row >= M) return;

    const float* lr = gate + (long long)row * EXP;
    float v0 = lr[lane];
    float v1 = lr[lane + 32];
    bool s0 = false, s1 = false;

    float sval[TOPK];
    int   sidx[TOPK];

#pragma unroll
    for (int t = 0; t < TOPK; ++t) {
        float a0 = s0 ? -INFINITY : v0;
        float a1 = s1 ? -INFINITY : v1;
        float cand; int cidx;
        if (a0 >= a1) { cand = a0; cidx = lane; }        // tie -> lower index
        else          { cand = a1; cidx = lane + 32; }
#pragma unroll
        for (int off = 16; off > 0; off >>= 1) {
            float ov = __shfl_down_sync(0xffffffffu, cand, off);
            int   oi = __shfl_down_sync(0xffffffffu, cidx, off);
            if (ov > cand || (ov == cand && oi < cidx)) { cand = ov; cidx = oi; }
        }
        cand = __shfl_sync(0xffffffffu, cand, 0);
        cidx = __shfl_sync(0xffffffffu, cidx, 0);
        sval[t] = cand;
        sidx[t] = cidx;
        if (cidx == lane)      s0 = true;
        if (cidx == lane + 32) s1 = true;
    }

    float mx = sval[0];
    float sum = 0.f;
#pragma unroll
    for (int t = 0; t < TOPK; ++t) sum += expf(sval[t] - mx);
    float inv = 1.0f / sum;

    sparse[(long long)row * EXP + lane]      = s0 ? expf(v0 - mx) * inv : 0.0f;
    sparse[(long long)row * EXP + lane + 32] = s1 ? expf(v1 - mx) * inv : 0.0f;
    if (lane < TOPK) idxf[(long long)row * TOPK + lane] = (float)sidx[lane];
}

// ---------------------------------------------------------------------------
// Outputs packed in reference tuple order into one fp32 buffer:
//   [0,            M*64)        sparse_logits
//   [M*64,         M*64+M*8)    indices (cast to float)
//   [M*64+M*8,     M*72+M*64)   gate_logit (raw logits incl. bias)
// ---------------------------------------------------------------------------
extern "C" void kernel_launch(void* const* d_in, const int* in_sizes, int n_in,
                              void* d_out, int out_size)
{
    const float* x = (const float*)d_in[0];
    const float* W = (const float*)d_in[1];
    const float* b = (const float*)d_in[2];

    const int M = in_sizes[0] / HDIM;   // 16384

    float* out    = (float*)d_out;
    float* sparse = out;
    float* idxf   = out + (long long)M * EXP;
    float* gate   = out + (long long)M * EXP + (long long)M * TOPK;

    gating_gemm_kernel<<<M / MT, 128>>>(x, W, b, gate, M);

    int threads = 256;
    int blocks  = (M * 32 + threads - 1) / threads;
    gating_topk_kernel<<<blocks, threads>>>(gate, sparse, idxf, M);
}

// round 5
// speedup vs baseline: 1.7111x; 1.7111x over previous
#include <cuda_runtime.h>
#include <cuda_bf16.h>
#include <math.h>
#include <stdint.h>

#define HDIM    4096
#define EXP     64
#define TOPK    8
#define CTAROWS 64
#define THREADS 128
#define KC      32
#define NCHUNK  (HDIM / KC)      // 128
#define FOLD    8                // fold acc_main -> sum every 8 iters

// SMEM layout (bytes). A/W tiles: bf16, row stride 80B.
#define OFF_BIAS 0
#define OFF_A    256
#define A_LVL    (CTAROWS * 80)          // 5120
#define OFF_W    (OFF_A + 3 * A_LVL)     // 15616
#define W_LVL    (EXP * 80)              // 5120
#define SMEM_SZ  (OFF_W + 3 * W_LVL)     // 30976
#define OFF_LOG  OFF_A                   // 64*66*4 = 16896 fits
#define LOGSTR   66

__device__ __nv_bfloat16 g_wsplit[3][EXP * HDIM];

// ---------------- helpers ----------------
static __device__ __forceinline__ uint32_t smem_u32(const void* p) {
    uint32_t a;
    asm("{ .reg .u64 t; cvta.to.shared.u64 t, %1; cvt.u32.u64 %0, t; }"
        : "=r"(a) : "l"(p));
    return a;
}
static __device__ __forceinline__ void split2(float a0, float a1,
                                              uint32_t& u0, uint32_t& u1, uint32_t& u2) {
    __nv_bfloat162 h0 = __floats2bfloat162_rn(a0, a1);
    float r0 = a0 - __bfloat162float(h0.x);
    float r1 = a1 - __bfloat162float(h0.y);
    __nv_bfloat162 h1 = __floats2bfloat162_rn(r0, r1);
    float s0 = r0 - __bfloat162float(h1.x);
    float s1 = r1 - __bfloat162float(h1.y);
    __nv_bfloat162 h2 = __floats2bfloat162_rn(s0, s1);
    u0 = reinterpret_cast<uint32_t&>(h0);
    u1 = reinterpret_cast<uint32_t&>(h1);
    u2 = reinterpret_cast<uint32_t&>(h2);
}
static __device__ __forceinline__ void ldsm4(uint32_t* r, uint32_t addr) {
    asm volatile("ldmatrix.sync.aligned.m8n8.x4.shared.b16 {%0,%1,%2,%3}, [%4];"
                 : "=r"(r[0]), "=r"(r[1]), "=r"(r[2]), "=r"(r[3]) : "r"(addr));
}
static __device__ __forceinline__ void mma16816(float* c, const uint32_t* a,
                                                const uint32_t* b) {
    asm volatile(
        "mma.sync.aligned.m16n8k16.row.col.f32.bf16.bf16.f32 "
        "{%0,%1,%2,%3}, {%4,%5,%6,%7}, {%8,%9}, {%0,%1,%2,%3};"
        : "+f"(c[0]), "+f"(c[1]), "+f"(c[2]), "+f"(c[3])
        : "r"(a[0]), "r"(a[1]), "r"(a[2]), "r"(a[3]), "r"(b[0]), "r"(b[1]));
}

// ---------------- W pre-split ----------------
__global__ void wsplit_kernel(const float* __restrict__ W) {
    int i = blockIdx.x * blockDim.x + threadIdx.x;
    if (i >= EXP * HDIM / 2) return;
    uint32_t u0, u1, u2;
    split2(W[2 * i], W[2 * i + 1], u0, u1, u2);
    reinterpret_cast<uint32_t*>(g_wsplit[0])[i] = u0;
    reinterpret_cast<uint32_t*>(g_wsplit[1])[i] = u1;
    reinterpret_cast<uint32_t*>(g_wsplit[2])[i] = u2;
}

// ---------------- fused gating ----------------
__global__ __launch_bounds__(THREADS, 2)
void gating_fused(const float* __restrict__ x, const float* __restrict__ b,
                  float* __restrict__ sparse, float* __restrict__ idxf,
                  float* __restrict__ gate)
{
    extern __shared__ char smem[];
    const uint32_t sb = smem_u32(smem);
    const int tid  = threadIdx.x;
    const int warp = tid >> 5;
    const int lane = tid & 31;
    const long long row_base = (long long)blockIdx.x * CTAROWS;

    if (tid < EXP) ((float*)(smem + OFF_BIAS))[tid] = b[tid];

    const float4* __restrict__ x4 = reinterpret_cast<const float4*>(x);

    const uint32_t a_lane = (uint32_t)((lane & 15) * 80 + (lane >> 4) * 16);
    const uint32_t b_lane = (uint32_t)(((lane & 7) + ((lane >> 4) << 3)) * 80 +
                                       ((lane >> 3) & 1) * 16);
    const uint32_t a_base = sb + OFF_A + (uint32_t)warp * 16 * 80 + a_lane;
    const uint32_t b_base = sb + OFF_W + b_lane;

    // accumulators: main term (b0*c0) chunked into fp32 master; small terms chained
    float acc_main[32], acc_small[32], sum[32];
#pragma unroll
    for (int i = 0; i < 32; ++i) { acc_main[i] = 0.f; acc_small[i] = 0.f; sum[i] = 0.f; }

    float4 xr[4];
    uint4  wr[6];
#pragma unroll
    for (int j = 0; j < 4; ++j) {
        int f = j * 128 + tid, r = f >> 3, q = f & 7;
        xr[j] = x4[(row_base + r) * (HDIM / 4) + q];
    }
#pragma unroll
    for (int j = 0; j < 6; ++j) {
        int fi = j * 128 + tid, lv = fi >> 8, rem = fi & 255, e = rem >> 2, kq = rem & 3;
        wr[j] = reinterpret_cast<const uint4*>(&g_wsplit[lv][e * HDIM])[kq];
    }

    for (int i = 0; i < NCHUNK; ++i) {
        __syncthreads();

        // ---- store x (convert to bf16x3) ----
#pragma unroll
        for (int j = 0; j < 4; ++j) {
            int f = j * 128 + tid, r = f >> 3, q = f & 7;
            uint2 v0, v1, v2;
            split2(xr[j].x, xr[j].y, v0.x, v1.x, v2.x);
            split2(xr[j].z, xr[j].w, v0.y, v1.y, v2.y);
            uint32_t so = (uint32_t)(r * 80 + q * 8);
            *(uint2*)(smem + OFF_A + 0 * A_LVL + so) = v0;
            *(uint2*)(smem + OFF_A + 1 * A_LVL + so) = v1;
            *(uint2*)(smem + OFF_A + 2 * A_LVL + so) = v2;
        }
        // ---- store W (copy) ----
#pragma unroll
        for (int j = 0; j < 6; ++j) {
            int fi = j * 128 + tid, lv = fi >> 8, rem = fi & 255, e = rem >> 2, kq = rem & 3;
            *(uint4*)(smem + OFF_W + lv * W_LVL + e * 80 + kq * 16) = wr[j];
        }
        __syncthreads();

        // ---- prefetch next chunk ----
        if (i + 1 < NCHUNK) {
#pragma unroll
            for (int j = 0; j < 4; ++j) {
                int f = j * 128 + tid, r = f >> 3, q = f & 7;
                xr[j] = x4[(row_base + r) * (HDIM / 4) + (i + 1) * 8 + q];
            }
#pragma unroll
            for (int j = 0; j < 6; ++j) {
                int fi = j * 128 + tid, lv = fi >> 8, rem = fi & 255, e = rem >> 2, kq = rem & 3;
                wr[j] = reinterpret_cast<const uint4*>(
                            &g_wsplit[lv][e * HDIM + (i + 1) * KC])[kq];
            }
        }

        // ---- compute ----
#pragma unroll
        for (int ks = 0; ks < 2; ++ks) {
            uint32_t afr[3][4];
#pragma unroll
            for (int lv = 0; lv < 3; ++lv)
                ldsm4(afr[lv], a_base + lv * A_LVL + ks * 32);

#pragma unroll
            for (int lvb = 0; lvb < 3; ++lvb) {
                uint32_t bfr[16];
#pragma unroll
                for (int q = 0; q < 4; ++q)
                    ldsm4(&bfr[q * 4], b_base + lvb * W_LVL + q * (16 * 80) + ks * 32);
                const int napass = 3 - lvb;   // 3,2,1
#pragma unroll
                for (int ap = 0; ap < 3; ++ap) {
                    if (ap < napass) {
                        float* dst = (lvb == 0 && ap == 0) ? acc_main : acc_small;
#pragma unroll
                        for (int nt = 0; nt < 8; ++nt)
                            mma16816(&dst[nt * 4], afr[ap],
                                     &bfr[(nt >> 1) * 4 + (nt & 1) * 2]);
                    }
                }
            }
        }

        // ---- fold main-term chunk into fp32 master (limits HMMA chain bias) ----
        if ((i & (FOLD - 1)) == (FOLD - 1)) {
#pragma unroll
            for (int q = 0; q < 32; ++q) { sum[q] += acc_main[q]; acc_main[q] = 0.f; }
        }
    }

    // ---- combine + write logits fragments to SMEM ----
    __syncthreads();
    {
        float* lg = (float*)(smem + OFF_LOG);
        int r0 = warp * 16 + (lane >> 2);
        int cm = (lane & 3) * 2;
#pragma unroll
        for (int nt = 0; nt < 8; ++nt) {
            int col = nt * 8 + cm;
            float t0 = sum[nt*4+0] + (acc_main[nt*4+0] + acc_small[nt*4+0]);
            float t1 = sum[nt*4+1] + (acc_main[nt*4+1] + acc_small[nt*4+1]);
            float t2 = sum[nt*4+2] + (acc_main[nt*4+2] + acc_small[nt*4+2]);
            float t3 = sum[nt*4+3] + (acc_main[nt*4+3] + acc_small[nt*4+3]);
            *(float2*)&lg[r0 * LOGSTR + col]       = make_float2(t0, t1);
            *(float2*)&lg[(r0 + 8) * LOGSTR + col] = make_float2(t2, t3);
        }
    }
    __syncthreads();

    // ---- per-row epilogue ----
    if (tid < CTAROWS) {
        const float* lg = (const float*)(smem + OFF_LOG) + tid * LOGSTR;
        const float* bs = (const float*)(smem + OFF_BIAS);
        float v[EXP];
#pragma unroll
        for (int c = 0; c < EXP; ++c) v[c] = lg[c] + bs[c];

        const long long grow = row_base + tid;
        float* gr = gate + grow * EXP;
#pragma unroll
        for (int c = 0; c < 16; ++c)
            ((float4*)gr)[c] = make_float4(v[4*c], v[4*c+1], v[4*c+2], v[4*c+3]);

        unsigned long long mask = 0ull;
        float sval[TOPK]; int sidx[TOPK];
        for (int t = 0; t < TOPK; ++t) {
            float best = -INFINITY; int bi = 0;
#pragma unroll
            for (int c = 0; c < EXP; ++c) {
                bool fr = !((mask >> c) & 1ull);
                if (fr && v[c] > best) { best = v[c]; bi = c; }
            }
            mask |= 1ull << bi;
            sval[t] = best; sidx[t] = bi;
        }
        float mx = sval[0], sumv = 0.f;
#pragma unroll
        for (int t = 0; t < TOPK; ++t) sumv += expf(sval[t] - mx);
        float inv = 1.0f / sumv;

        float* sr = sparse + grow * EXP;
#pragma unroll
        for (int c = 0; c < EXP; ++c) sr[c] = 0.0f;
        for (int t = 0; t < TOPK; ++t) {
            sr[sidx[t]] = expf(sval[t] - mx) * inv;
            idxf[grow * TOPK + t] = (float)sidx[t];
        }
    }
}

extern "C" void kernel_launch(void* const* d_in, const int* in_sizes, int n_in,
                              void* d_out, int out_size)
{
    const float* x = (const float*)d_in[0];
    const float* W = (const float*)d_in[1];
    const float* b = (const float*)d_in[2];

    const int M = in_sizes[0] / HDIM;     // 16384

    float* out    = (float*)d_out;
    float* sparse = out;
    float* idxf   = out + (long long)M * EXP;
    float* gate   = out + (long long)M * EXP + (long long)M * TOPK;

    wsplit_kernel<<<(EXP * HDIM / 2 + 255) / 256, 256>>>(W);
    gating_fused<<<M / CTAROWS, THREADS, SMEM_SZ>>>(x, b, sparse, idxf, gate);
}

// round 6
// speedup vs baseline: 1.7125x; 1.0008x over previous
#include <cuda_runtime.h>
#include <cuda_bf16.h>
#include <math.h>
#include <stdint.h>

#define HDIM    4096
#define EXP     64
#define TOPK    8
#define CTAROWS 64
#define THREADS 128
#define KC      32
#define NCHUNK  (HDIM / KC)      // 128
#define FOLD    4

// SMEM: A tiles only (bf16x3, 64 rows x 32k, 80B row stride), bias, logits alias.
#define OFF_BIAS 0
#define OFF_A    256
#define A_LVL    (CTAROWS * 80)          // 5120
#define OFF_LOG  OFF_A
#define LOGSTR   66
#define SMEM_SZ  (OFF_LOG + CTAROWS * LOGSTR * 4)   // 17152 (>= 256+3*A_LVL=15616)

// W in B-fragment order: [chunk][ks][lvb][nt(8)][lane(32)] -> uint2{b0,b1}
#define NFRAG (NCHUNK * 2 * 3 * 8 * 32)
__device__ uint2 g_wfrag[NFRAG];

// ---------------- helpers ----------------
static __device__ __forceinline__ uint32_t smem_u32(const void* p) {
    uint32_t a;
    asm("{ .reg .u64 t; cvta.to.shared.u64 t, %1; cvt.u32.u64 %0, t; }"
        : "=r"(a) : "l"(p));
    return a;
}
static __device__ __forceinline__ void split2(float a0, float a1,
                                              uint32_t& u0, uint32_t& u1, uint32_t& u2) {
    __nv_bfloat162 h0 = __floats2bfloat162_rn(a0, a1);
    float r0 = a0 - __bfloat162float(h0.x);
    float r1 = a1 - __bfloat162float(h0.y);
    __nv_bfloat162 h1 = __floats2bfloat162_rn(r0, r1);
    float s0 = r0 - __bfloat162float(h1.x);
    float s1 = r1 - __bfloat162float(h1.y);
    __nv_bfloat162 h2 = __floats2bfloat162_rn(s0, s1);
    u0 = reinterpret_cast<uint32_t&>(h0);
    u1 = reinterpret_cast<uint32_t&>(h1);
    u2 = reinterpret_cast<uint32_t&>(h2);
}
static __device__ __forceinline__ void ldsm4(uint32_t* r, uint32_t addr) {
    asm volatile("ldmatrix.sync.aligned.m8n8.x4.shared.b16 {%0,%1,%2,%3}, [%4];"
                 : "=r"(r[0]), "=r"(r[1]), "=r"(r[2]), "=r"(r[3]) : "r"(addr));
}
static __device__ __forceinline__ void mma16816(float* c, const uint32_t* a,
                                                const uint32_t* b) {
    asm volatile(
        "mma.sync.aligned.m16n8k16.row.col.f32.bf16.bf16.f32 "
        "{%0,%1,%2,%3}, {%4,%5,%6,%7}, {%8,%9}, {%0,%1,%2,%3};"
        : "+f"(c[0]), "+f"(c[1]), "+f"(c[2]), "+f"(c[3])
        : "r"(a[0]), "r"(a[1]), "r"(a[2]), "r"(a[3]), "r"(b[0]), "r"(b[1]));
}

// ---------------- W repack: fp32 -> bf16x3 B-fragments ----------------
__global__ void wfrag_kernel(const float* __restrict__ W) {
    int idx = blockIdx.x * blockDim.x + threadIdx.x;
    if (idx >= NFRAG) return;
    int lane = idx & 31;
    int nt   = (idx >> 5) & 7;
    int t    = idx >> 8;
    int lvb  = t % 3; t /= 3;
    int ks   = t & 1;
    int ch   = t >> 1;
    int e = nt * 8 + (lane >> 2);
    int k = ch * KC + ks * 16 + (lane & 3) * 2;
    const float* w = W + (long long)e * HDIM + k;
    uint32_t u0a, u1a, u2a, u0b, u1b, u2b;
    split2(w[0], w[1], u0a, u1a, u2a);
    split2(w[8], w[9], u0b, u1b, u2b);
    uint2 v;
    v.x = (lvb == 0) ? u0a : (lvb == 1) ? u1a : u2a;
    v.y = (lvb == 0) ? u0b : (lvb == 1) ? u1b : u2b;
    g_wfrag[idx] = v;
}

// ---------------- fused gating ----------------
__global__ __launch_bounds__(THREADS, 2)
void gating_fused(const float* __restrict__ x, const float* __restrict__ b,
                  float* __restrict__ sparse, float* __restrict__ idxf,
                  float* __restrict__ gate)
{
    extern __shared__ char smem[];
    const uint32_t sb = smem_u32(smem);
    const int tid  = threadIdx.x;
    const int warp = tid >> 5;
    const int lane = tid & 31;
    const int rg = warp & 1;      // row group: rows rg*32..+32
    const int eg = warp >> 1;     // expert group: experts eg*32..+32
    const long long row_base = (long long)blockIdx.x * CTAROWS;

    if (tid < EXP) ((float*)(smem + OFF_BIAS))[tid] = b[tid];

    const float4* __restrict__ x4 = reinterpret_cast<const float4*>(x);

    // A ldmatrix lane address (16 rows per m-tile, 80B stride)
    const uint32_t a_lane = (uint32_t)((lane & 15) * 80 + (lane >> 4) * 16);
    const uint32_t a_base = sb + OFF_A + (uint32_t)rg * (32 * 80) + a_lane;

    float acc[32], sum[32];
#pragma unroll
    for (int i = 0; i < 32; ++i) { acc[i] = 0.f; sum[i] = 0.f; }

    // x prefetch for chunk 0
    float4 xr[4];
#pragma unroll
    for (int j = 0; j < 4; ++j) {
        int f = j * 128 + tid, r = f >> 3, q = f & 7;
        xr[j] = x4[(row_base + r) * (HDIM / 4) + q];
    }

    // B fragment double buffer; preload stage (chunk0, ks0, lvb0)
    uint2 bf[2][4];
    {
        const uint2* p0 = g_wfrag + (long long)(eg * 4) * 32 + lane;
#pragma unroll
        for (int nt = 0; nt < 4; ++nt) bf[0][nt] = p0[nt * 32];
    }
    int pp = 0;

    for (int i = 0; i < NCHUNK; ++i) {
        __syncthreads();

        // ---- convert + store x tile (3 bf16 levels) ----
#pragma unroll
        for (int j = 0; j < 4; ++j) {
            int f = j * 128 + tid, r = f >> 3, q = f & 7;
            uint2 v0, v1, v2;
            split2(xr[j].x, xr[j].y, v0.x, v1.x, v2.x);
            split2(xr[j].z, xr[j].w, v0.y, v1.y, v2.y);
            uint32_t so = (uint32_t)(r * 80 + q * 8);
            *(uint2*)(smem + OFF_A + 0 * A_LVL + so) = v0;
            *(uint2*)(smem + OFF_A + 1 * A_LVL + so) = v1;
            *(uint2*)(smem + OFF_A + 2 * A_LVL + so) = v2;
        }
        __syncthreads();

        // ---- prefetch next x chunk ----
        if (i + 1 < NCHUNK) {
#pragma unroll
            for (int j = 0; j < 4; ++j) {
                int f = j * 128 + tid, r = f >> 3, q = f & 7;
                xr[j] = x4[(row_base + r) * (HDIM / 4) + (i + 1) * 8 + q];
            }
        }

        // ---- compute: 2 k16 steps x 3 B levels, B frags via pipelined LDG ----
#pragma unroll
        for (int ks = 0; ks < 2; ++ks) {
            uint32_t afr[3][2][4];
#pragma unroll
            for (int lv = 0; lv < 3; ++lv)
#pragma unroll
                for (int mt = 0; mt < 2; ++mt)
                    ldsm4(afr[lv][mt], a_base + lv * A_LVL + mt * (16 * 80) + ks * 32);

#pragma unroll
            for (int lvb = 0; lvb < 3; ++lvb) {
                // preload next stage's B fragments
                int nks = ks, nlvb = lvb + 1, nch = i;
                if (nlvb == 3) {
                    nlvb = 0; nks = ks + 1;
                    if (nks == 2) { nks = 0; nch = (i + 1 < NCHUNK) ? i + 1 : i; }
                }
                const uint2* np = g_wfrag +
                    ((long long)(((nch * 2 + nks) * 3 + nlvb) * 8 + eg * 4) * 32) + lane;
#pragma unroll
                for (int nt = 0; nt < 4; ++nt) bf[pp ^ 1][nt] = np[nt * 32];

                const int na = 3 - lvb;   // A levels paired with this B level
#pragma unroll
                for (int ap = 0; ap < 3; ++ap) {
                    if (ap < na) {
#pragma unroll
                        for (int mt = 0; mt < 2; ++mt)
#pragma unroll
                            for (int nt = 0; nt < 4; ++nt)
                                mma16816(&acc[(mt * 4 + nt) * 4], afr[ap][mt],
                                         (const uint32_t*)&bf[pp][nt]);
                    }
                }
                pp ^= 1;
            }
        }

        // ---- fold into fp32 master (bounds HMMA chain bias) ----
        if ((i & (FOLD - 1)) == (FOLD - 1)) {
#pragma unroll
            for (int q = 0; q < 32; ++q) { sum[q] += acc[q]; acc[q] = 0.f; }
        }
    }

    // ---- write logits to SMEM (aliases tile region) ----
    __syncthreads();
    {
        float* lg = (float*)(smem + OFF_LOG);
#pragma unroll
        for (int mt = 0; mt < 2; ++mt) {
            int r0 = rg * 32 + mt * 16 + (lane >> 2);
#pragma unroll
            for (int nt = 0; nt < 4; ++nt) {
                int col = eg * 32 + nt * 8 + (lane & 3) * 2;
                int a0 = (mt * 4 + nt) * 4;
                float t0 = sum[a0 + 0] + acc[a0 + 0];
                float t1 = sum[a0 + 1] + acc[a0 + 1];
                float t2 = sum[a0 + 2] + acc[a0 + 2];
                float t3 = sum[a0 + 3] + acc[a0 + 3];
                *(float2*)&lg[r0 * LOGSTR + col]       = make_float2(t0, t1);
                *(float2*)&lg[(r0 + 8) * LOGSTR + col] = make_float2(t2, t3);
            }
        }
    }
    __syncthreads();

    // ---- per-row epilogue: bias + gate + top-8 + masked softmax ----
    if (tid < CTAROWS) {
        const float* lg = (const float*)(smem + OFF_LOG) + tid * LOGSTR;
        const float* bs = (const float*)(smem + OFF_BIAS);
        float v[EXP];
#pragma unroll
        for (int c = 0; c < EXP; ++c) v[c] = lg[c] + bs[c];

        const long long grow = row_base + tid;
        float* gr = gate + grow * EXP;
#pragma unroll
        for (int c = 0; c < 16; ++c)
            ((float4*)gr)[c] = make_float4(v[4*c], v[4*c+1], v[4*c+2], v[4*c+3]);

        unsigned long long mask = 0ull;
        float sval[TOPK]; int sidx[TOPK];
        for (int t = 0; t < TOPK; ++t) {
            float best = -INFINITY; int bi = 0;
#pragma unroll
            for (int c = 0; c < EXP; ++c) {
                bool fr = !((mask >> c) & 1ull);
                if (fr && v[c] > best) { best = v[c]; bi = c; }   // tie -> lower idx
            }
            mask |= 1ull << bi;
            sval[t] = best; sidx[t] = bi;
        }
        float mx = sval[0], sumv = 0.f;
#pragma unroll
        for (int t = 0; t < TOPK; ++t) sumv += expf(sval[t] - mx);
        float inv = 1.0f / sumv;

        float* sr = sparse + grow * EXP;
#pragma unroll
        for (int c = 0; c < EXP; ++c) sr[c] = 0.0f;
        for (int t = 0; t < TOPK; ++t) {
            sr[sidx[t]] = expf(sval[t] - mx) * inv;
            idxf[grow * TOPK + t] = (float)sidx[t];
        }
    }
}

extern "C" void kernel_launch(void* const* d_in, const int* in_sizes, int n_in,
                              void* d_out, int out_size)
{
    const float* x = (const float*)d_in[0];
    const float* W = (const float*)d_in[1];
    const float* b = (const float*)d_in[2];

    const int M = in_sizes[0] / HDIM;     // 16384

    float* out    = (float*)d_out;
    float* sparse = out;
    float* idxf   = out + (long long)M * EXP;
    float* gate   = out + (long long)M * EXP + (long long)M * TOPK;

    wfrag_kernel<<<(NFRAG + 255) / 256, 256>>>(W);
    gating_fused<<<M / CTAROWS, THREADS, SMEM_SZ>>>(x, b, sparse, idxf, gate);
}

// round 7
// speedup vs baseline: 1.8188x; 1.0621x over previous
#include <cuda_runtime.h>
#include <cuda_bf16.h>
#include <math.h>
#include <stdint.h>

#define HDIM    4096
#define EXP     64
#define TOPK    8
#define CTAROWS 64
#define THREADS 256
#define KC      32
#define NCHUNK  (HDIM / KC)      // 128
#define FOLD    4

// SMEM: double-buffered A tiles (bf16x3, 64 rows x 32k, 80B stride) + bias.
#define OFF_BIAS 0
#define OFF_A    256
#define A_LVL    (CTAROWS * 80)          // 5120
#define A_STG    (3 * A_LVL)             // 15360
#define SMEM_SZ  (OFF_A + 2 * A_STG)     // 30976
#define OFF_LOG  OFF_A                   // 64*66*4 = 16896 fits
#define LOGSTR   66

// W in B-fragment order: [chunk][ks][lvb][nt(8)][lane(32)] -> uint2{b0,b1}
#define NFRAG (NCHUNK * 2 * 3 * 8 * 32)
__device__ uint2 g_wfrag[NFRAG];

// ---------------- helpers ----------------
static __device__ __forceinline__ uint32_t smem_u32(const void* p) {
    uint32_t a;
    asm("{ .reg .u64 t; cvta.to.shared.u64 t, %1; cvt.u32.u64 %0, t; }"
        : "=r"(a) : "l"(p));
    return a;
}
static __device__ __forceinline__ void split2(float a0, float a1,
                                              uint32_t& u0, uint32_t& u1, uint32_t& u2) {
    __nv_bfloat162 h0 = __floats2bfloat162_rn(a0, a1);
    float r0 = a0 - __bfloat162float(h0.x);
    float r1 = a1 - __bfloat162float(h0.y);
    __nv_bfloat162 h1 = __floats2bfloat162_rn(r0, r1);
    float s0 = r0 - __bfloat162float(h1.x);
    float s1 = r1 - __bfloat162float(h1.y);
    __nv_bfloat162 h2 = __floats2bfloat162_rn(s0, s1);
    u0 = reinterpret_cast<uint32_t&>(h0);
    u1 = reinterpret_cast<uint32_t&>(h1);
    u2 = reinterpret_cast<uint32_t&>(h2);
}
static __device__ __forceinline__ void ldsm4(uint32_t* r, uint32_t addr) {
    asm volatile("ldmatrix.sync.aligned.m8n8.x4.shared.b16 {%0,%1,%2,%3}, [%4];"
                 : "=r"(r[0]), "=r"(r[1]), "=r"(r[2]), "=r"(r[3]) : "r"(addr));
}
static __device__ __forceinline__ void mma16816(float* c, const uint32_t* a,
                                                const uint32_t* b) {
    asm volatile(
        "mma.sync.aligned.m16n8k16.row.col.f32.bf16.bf16.f32 "
        "{%0,%1,%2,%3}, {%4,%5,%6,%7}, {%8,%9}, {%0,%1,%2,%3};"
        : "+f"(c[0]), "+f"(c[1]), "+f"(c[2]), "+f"(c[3])
        : "r"(a[0]), "r"(a[1]), "r"(a[2]), "r"(a[3]), "r"(b[0]), "r"(b[1]));
}

// ---------------- W repack: fp32 -> bf16x3 B-fragments ----------------
__global__ void wfrag_kernel(const float* __restrict__ W) {
    int idx = blockIdx.x * blockDim.x + threadIdx.x;
    if (idx >= NFRAG) return;
    int lane = idx & 31;
    int nt   = (idx >> 5) & 7;
    int t    = idx >> 8;
    int lvb  = t % 3; t /= 3;
    int ks   = t & 1;
    int ch   = t >> 1;
    int e = nt * 8 + (lane >> 2);
    int k = ch * KC + ks * 16 + (lane & 3) * 2;
    const float* w = W + (long long)e * HDIM + k;
    uint32_t u0a, u1a, u2a, u0b, u1b, u2b;
    split2(w[0], w[1], u0a, u1a, u2a);
    split2(w[8], w[9], u0b, u1b, u2b);
    uint2 v;
    v.x = (lvb == 0) ? u0a : (lvb == 1) ? u1a : u2a;
    v.y = (lvb == 0) ? u0b : (lvb == 1) ? u1b : u2b;
    g_wfrag[idx] = v;
}

// ---------------- fused gating ----------------
__global__ __launch_bounds__(THREADS, 2)
void gating_fused(const float* __restrict__ x, const float* __restrict__ b,
                  float* __restrict__ sparse, float* __restrict__ idxf,
                  float* __restrict__ gate)
{
    extern __shared__ char smem[];
    const uint32_t sb = smem_u32(smem);
    const int tid  = threadIdx.x;
    const int warp = tid >> 5;
    const int lane = tid & 31;
    const int rg = warp & 1;      // rows rg*32..+32
    const int eg = warp >> 1;     // experts eg*16..+16 (nt tiles 2eg, 2eg+1)
    const long long row_base = (long long)blockIdx.x * CTAROWS;

    if (tid < EXP) ((float*)(smem + OFF_BIAS))[tid] = b[tid];

    const float4* __restrict__ x4 = reinterpret_cast<const float4*>(x);

    const uint32_t a_lane = (uint32_t)((lane & 15) * 80 + (lane >> 4) * 16);
    const uint32_t a_base = sb + OFF_A + (uint32_t)rg * (32 * 80) + a_lane;

    float acc[16], sum[16];
#pragma unroll
    for (int i = 0; i < 16; ++i) { acc[i] = 0.f; sum[i] = 0.f; }

    // ---- prologue: load + convert chunk 0 into stage 0 ----
    float4 xr[2];
#pragma unroll
    for (int j = 0; j < 2; ++j) {
        int f = j * 256 + tid, r = f >> 3, q = f & 7;
        xr[j] = x4[(row_base + r) * (HDIM / 4) + q];
    }
#pragma unroll
    for (int j = 0; j < 2; ++j) {
        int f = j * 256 + tid, r = f >> 3, q = f & 7;
        uint2 v0, v1, v2;
        split2(xr[j].x, xr[j].y, v0.x, v1.x, v2.x);
        split2(xr[j].z, xr[j].w, v0.y, v1.y, v2.y);
        uint32_t so = (uint32_t)(r * 80 + q * 8);
        *(uint2*)(smem + OFF_A + 0 * A_LVL + so) = v0;
        *(uint2*)(smem + OFF_A + 1 * A_LVL + so) = v1;
        *(uint2*)(smem + OFF_A + 2 * A_LVL + so) = v2;
    }

    // B fragment double buffer; preload stage (chunk0, ks0, lvb0)
    uint2 bf[2][2];
    {
        const uint2* p0 = g_wfrag + (long long)(eg * 2) * 32 + lane;
        bf[0][0] = p0[0];
        bf[0][1] = p0[32];
    }
    int pp = 0;

    __syncthreads();

    for (int i = 0; i < NCHUNK; ++i) {
        const int stg = i & 1;
        const uint32_t a_st = a_base + (uint32_t)stg * A_STG;

        // ---- prefetch x for chunk i+1 ----
        if (i + 1 < NCHUNK) {
#pragma unroll
            for (int j = 0; j < 2; ++j) {
                int f = j * 256 + tid, r = f >> 3, q = f & 7;
                xr[j] = x4[(row_base + r) * (HDIM / 4) + (i + 1) * 8 + q];
            }
        }

        // ---- compute from stage stg; B frags via pipelined LDG ----
#pragma unroll
        for (int ks = 0; ks < 2; ++ks) {
            uint32_t afr[3][2][4];
#pragma unroll
            for (int lv = 0; lv < 3; ++lv)
#pragma unroll
                for (int mt = 0; mt < 2; ++mt)
                    ldsm4(afr[lv][mt], a_st + lv * A_LVL + mt * (16 * 80) + ks * 32);

#pragma unroll
            for (int lvb = 0; lvb < 3; ++lvb) {
                int nks = ks, nlvb = lvb + 1, nch = i;
                if (nlvb == 3) {
                    nlvb = 0; nks = ks + 1;
                    if (nks == 2) { nks = 0; nch = (i + 1 < NCHUNK) ? i + 1 : i; }
                }
                const uint2* np = g_wfrag +
                    ((long long)(((nch * 2 + nks) * 3 + nlvb) * 8 + eg * 2) * 32) + lane;
                bf[pp ^ 1][0] = np[0];
                bf[pp ^ 1][1] = np[32];

                const int na = 3 - lvb;
#pragma unroll
                for (int ap = 0; ap < 3; ++ap) {
                    if (ap < na) {
#pragma unroll
                        for (int mt = 0; mt < 2; ++mt)
#pragma unroll
                            for (int nt = 0; nt < 2; ++nt)
                                mma16816(&acc[(mt * 2 + nt) * 4], afr[ap][mt],
                                         (const uint32_t*)&bf[pp][nt]);
                    }
                }
                pp ^= 1;
            }
        }

        // ---- convert chunk i+1 into the other stage ----
        if (i + 1 < NCHUNK) {
            const uint32_t dst = OFF_A + (uint32_t)(stg ^ 1) * A_STG;
#pragma unroll
            for (int j = 0; j < 2; ++j) {
                int f = j * 256 + tid, r = f >> 3, q = f & 7;
                uint2 v0, v1, v2;
                split2(xr[j].x, xr[j].y, v0.x, v1.x, v2.x);
                split2(xr[j].z, xr[j].w, v0.y, v1.y, v2.y);
                uint32_t so = (uint32_t)(r * 80 + q * 8);
                *(uint2*)(smem + dst + 0 * A_LVL + so) = v0;
                *(uint2*)(smem + dst + 1 * A_LVL + so) = v1;
                *(uint2*)(smem + dst + 2 * A_LVL + so) = v2;
            }
        }

        // ---- fold into fp32 master ----
        if ((i & (FOLD - 1)) == (FOLD - 1)) {
#pragma unroll
            for (int q = 0; q < 16; ++q) { sum[q] += acc[q]; acc[q] = 0.f; }
        }

        __syncthreads();
    }

    // ---- write logits to SMEM (aliases tile region) ----
    {
        float* lg = (float*)(smem + OFF_LOG);
#pragma unroll
        for (int mt = 0; mt < 2; ++mt) {
            int r0 = rg * 32 + mt * 16 + (lane >> 2);
#pragma unroll
            for (int nt = 0; nt < 2; ++nt) {
                int col = eg * 16 + nt * 8 + (lane & 3) * 2;
                int a0 = (mt * 2 + nt) * 4;
                float t0 = sum[a0 + 0] + acc[a0 + 0];
                float t1 = sum[a0 + 1] + acc[a0 + 1];
                float t2 = sum[a0 + 2] + acc[a0 + 2];
                float t3 = sum[a0 + 3] + acc[a0 + 3];
                *(float2*)&lg[r0 * LOGSTR + col]       = make_float2(t0, t1);
                *(float2*)&lg[(r0 + 8) * LOGSTR + col] = make_float2(t2, t3);
            }
        }
    }
    __syncthreads();

    // ---- per-row epilogue: bias + gate + top-8 + masked softmax ----
    if (tid < CTAROWS) {
        const float* lg = (const float*)(smem + OFF_LOG) + tid * LOGSTR;
        const float* bs = (const float*)(smem + OFF_BIAS);
        float v[EXP];
#pragma unroll
        for (int c = 0; c < EXP; ++c) v[c] = lg[c] + bs[c];

        const long long grow = row_base + tid;
        float* gr = gate + grow * EXP;
#pragma unroll
        for (int c = 0; c < 16; ++c)
            ((float4*)gr)[c] = make_float4(v[4*c], v[4*c+1], v[4*c+2], v[4*c+3]);

        unsigned long long mask = 0ull;
        float sval[TOPK]; int sidx[TOPK];
        for (int t = 0; t < TOPK; ++t) {
            float best = -INFINITY; int bi = 0;
#pragma unroll
            for (int c = 0; c < EXP; ++c) {
                bool fr = !((mask >> c) & 1ull);
                if (fr && v[c] > best) { best = v[c]; bi = c; }   // tie -> lower idx
            }
            mask |= 1ull << bi;
            sval[t] = best; sidx[t] = bi;
        }
        float mx = sval[0], sumv = 0.f;
#pragma unroll
        for (int t = 0; t < TOPK; ++t) sumv += expf(sval[t] - mx);
        float inv = 1.0f / sumv;

        float* sr = sparse + grow * EXP;
#pragma unroll
        for (int c = 0; c < EXP; ++c) sr[c] = 0.0f;
        for (int t = 0; t < TOPK; ++t) {
            sr[sidx[t]] = expf(sval[t] - mx) * inv;
            idxf[grow * TOPK + t] = (float)sidx[t];
        }
    }
}

extern "C" void kernel_launch(void* const* d_in, const int* in_sizes, int n_in,
                              void* d_out, int out_size)
{
    const float* x = (const float*)d_in[0];
    const float* W = (const float*)d_in[1];
    const float* b = (const float*)d_in[2];

    const int M = in_sizes[0] / HDIM;     // 16384

    float* out    = (float*)d_out;
    float* sparse = out;
    float* idxf   = out + (long long)M * EXP;
    float* gate   = out + (long long)M * EXP + (long long)M * TOPK;

    wfrag_kernel<<<(NFRAG + 255) / 256, 256>>>(W);
    gating_fused<<<M / CTAROWS, THREADS, SMEM_SZ>>>(x, b, sparse, idxf, gate);
}

// round 8
// speedup vs baseline: 1.8214x; 1.0014x over previous
#include <cuda_runtime.h>
#include <cuda_bf16.h>
#include <math.h>
#include <stdint.h>

#define HDIM    4096
#define EXP     64
#define TOPK    8
#define CTAROWS 64
#define THREADS 256
#define KC      32
#define NCHUNK  (HDIM / KC)      // 128
#define FOLD    4

// SMEM: double-buffered A tiles (bf16x3, 64 rows x 32k, 80B stride) + bias.
#define OFF_BIAS 0
#define OFF_A    256
#define A_LVL    (CTAROWS * 80)          // 5120
#define A_STG    (3 * A_LVL)             // 15360
#define SMEM_SZ  (OFF_A + 2 * A_STG)     // 30976
#define OFF_LOG  OFF_A                   // 64*66*4 = 16896 fits
#define LOGSTR   66

// W in B-fragment order: [chunk][ks][lvb][nt(8)][lane(32)] -> uint2{b0,b1}
#define NFRAG (NCHUNK * 2 * 3 * 8 * 32)
__device__ uint2 g_wfrag[NFRAG];

// ---------------- helpers ----------------
static __device__ __forceinline__ uint32_t smem_u32(const void* p) {
    uint32_t a;
    asm("{ .reg .u64 t; cvta.to.shared.u64 t, %1; cvt.u32.u64 %0, t; }"
        : "=r"(a) : "l"(p));
    return a;
}
static __device__ __forceinline__ void split2(float a0, float a1,
                                              uint32_t& u0, uint32_t& u1, uint32_t& u2) {
    __nv_bfloat162 h0 = __floats2bfloat162_rn(a0, a1);
    float r0 = a0 - __bfloat162float(h0.x);
    float r1 = a1 - __bfloat162float(h0.y);
    __nv_bfloat162 h1 = __floats2bfloat162_rn(r0, r1);
    float s0 = r0 - __bfloat162float(h1.x);
    float s1 = r1 - __bfloat162float(h1.y);
    __nv_bfloat162 h2 = __floats2bfloat162_rn(s0, s1);
    u0 = reinterpret_cast<uint32_t&>(h0);
    u1 = reinterpret_cast<uint32_t&>(h1);
    u2 = reinterpret_cast<uint32_t&>(h2);
}
static __device__ __forceinline__ void ldsm4(uint32_t* r, uint32_t addr) {
    asm volatile("ldmatrix.sync.aligned.m8n8.x4.shared.b16 {%0,%1,%2,%3}, [%4];"
                 : "=r"(r[0]), "=r"(r[1]), "=r"(r[2]), "=r"(r[3]) : "r"(addr));
}
static __device__ __forceinline__ void mma16816(float* c, const uint32_t* a,
                                                const uint32_t* b) {
    asm volatile(
        "mma.sync.aligned.m16n8k16.row.col.f32.bf16.bf16.f32 "
        "{%0,%1,%2,%3}, {%4,%5,%6,%7}, {%8,%9}, {%0,%1,%2,%3};"
        : "+f"(c[0]), "+f"(c[1]), "+f"(c[2]), "+f"(c[3])
        : "r"(a[0]), "r"(a[1]), "r"(a[2]), "r"(a[3]), "r"(b[0]), "r"(b[1]));
}

// ---------------- W repack: fp32 -> bf16x3 B-fragments ----------------
__global__ void wfrag_kernel(const float* __restrict__ W) {
    int idx = blockIdx.x * blockDim.x + threadIdx.x;
    if (idx >= NFRAG) return;
    int lane = idx & 31;
    int nt   = (idx >> 5) & 7;
    int t    = idx >> 8;
    int lvb  = t % 3; t /= 3;
    int ks   = t & 1;
    int ch   = t >> 1;
    int e = nt * 8 + (lane >> 2);
    int k = ch * KC + ks * 16 + (lane & 3) * 2;
    const float* w = W + (long long)e * HDIM + k;
    uint32_t u0a, u1a, u2a, u0b, u1b, u2b;
    split2(w[0], w[1], u0a, u1a, u2a);
    split2(w[8], w[9], u0b, u1b, u2b);
    uint2 v;
    v.x = (lvb == 0) ? u0a : (lvb == 1) ? u1a : u2a;
    v.y = (lvb == 0) ? u0b : (lvb == 1) ? u1b : u2b;
    g_wfrag[idx] = v;
}

// ---------------- fused gating ----------------
__global__ __launch_bounds__(THREADS, 2)
void gating_fused(const float* __restrict__ x, const float* __restrict__ b,
                  float* __restrict__ sparse, float* __restrict__ idxf,
                  float* __restrict__ gate)
{
    extern __shared__ char smem[];
    const uint32_t sb = smem_u32(smem);
    const int tid  = threadIdx.x;
    const int warp = tid >> 5;
    const int lane = tid & 31;
    const int rg = warp & 1;      // rows rg*32..+32
    const int eg = warp >> 1;     // experts eg*16..+16 (nt tiles 2eg, 2eg+1)
    const long long row_base = (long long)blockIdx.x * CTAROWS;

    if (tid < EXP) ((float*)(smem + OFF_BIAS))[tid] = b[tid];

    const float4* __restrict__ x4 = reinterpret_cast<const float4*>(x);

    const uint32_t a_lane = (uint32_t)((lane & 15) * 80 + (lane >> 4) * 16);
    const uint32_t a_base = sb + OFF_A + (uint32_t)rg * (32 * 80) + a_lane;

    float acc[16], sum[16];
#pragma unroll
    for (int i = 0; i < 16; ++i) { acc[i] = 0.f; sum[i] = 0.f; }

    // ---- prologue: load + convert chunk 0 into stage 0 ----
    float4 xr[2];
#pragma unroll
    for (int j = 0; j < 2; ++j) {
        int f = j * 256 + tid, r = f >> 3, q = f & 7;
        xr[j] = x4[(row_base + r) * (HDIM / 4) + q];
    }
#pragma unroll
    for (int j = 0; j < 2; ++j) {
        int f = j * 256 + tid, r = f >> 3, q = f & 7;
        uint2 v0, v1, v2;
        split2(xr[j].x, xr[j].y, v0.x, v1.x, v2.x);
        split2(xr[j].z, xr[j].w, v0.y, v1.y, v2.y);
        uint32_t so = (uint32_t)(r * 80 + q * 8);
        *(uint2*)(smem + OFF_A + 0 * A_LVL + so) = v0;
        *(uint2*)(smem + OFF_A + 1 * A_LVL + so) = v1;
        *(uint2*)(smem + OFF_A + 2 * A_LVL + so) = v2;
    }

    // B fragment double buffer; preload stage (chunk0, ks0, lvb0)
    uint2 bf[2][2];
    {
        const uint2* p0 = g_wfrag + (long long)(eg * 2) * 32 + lane;
        bf[0][0] = p0[0];
        bf[0][1] = p0[32];
    }
    int pp = 0;

    __syncthreads();

    for (int i = 0; i < NCHUNK; ++i) {
        const int stg = i & 1;
        const uint32_t a_st = a_base + (uint32_t)stg * A_STG;

        // ---- prefetch x for chunk i+1 ----
        if (i + 1 < NCHUNK) {
#pragma unroll
            for (int j = 0; j < 2; ++j) {
                int f = j * 256 + tid, r = f >> 3, q = f & 7;
                xr[j] = x4[(row_base + r) * (HDIM / 4) + (i + 1) * 8 + q];
            }
        }

        // ---- compute from stage stg; B frags via pipelined LDG ----
#pragma unroll
        for (int ks = 0; ks < 2; ++ks) {
            uint32_t afr[3][2][4];
#pragma unroll
            for (int lv = 0; lv < 3; ++lv)
#pragma unroll
                for (int mt = 0; mt < 2; ++mt)
                    ldsm4(afr[lv][mt], a_st + lv * A_LVL + mt * (16 * 80) + ks * 32);

#pragma unroll
            for (int lvb = 0; lvb < 3; ++lvb) {
                int nks = ks, nlvb = lvb + 1, nch = i;
                if (nlvb == 3) {
                    nlvb = 0; nks = ks + 1;
                    if (nks == 2) { nks = 0; nch = (i + 1 < NCHUNK) ? i + 1 : i; }
                }
                const uint2* np = g_wfrag +
                    ((long long)(((nch * 2 + nks) * 3 + nlvb) * 8 + eg * 2) * 32) + lane;
                bf[pp ^ 1][0] = np[0];
                bf[pp ^ 1][1] = np[32];

                const int na = 3 - lvb;
#pragma unroll
                for (int ap = 0; ap < 3; ++ap) {
                    if (ap < na) {
#pragma unroll
                        for (int mt = 0; mt < 2; ++mt)
#pragma unroll
                            for (int nt = 0; nt < 2; ++nt)
                                mma16816(&acc[(mt * 2 + nt) * 4], afr[ap][mt],
                                         (const uint32_t*)&bf[pp][nt]);
                    }
                }
                pp ^= 1;
            }
        }

        // ---- convert chunk i+1 into the other stage ----
        if (i + 1 < NCHUNK) {
            const uint32_t dst = OFF_A + (uint32_t)(stg ^ 1) * A_STG;
#pragma unroll
            for (int j = 0; j < 2; ++j) {
                int f = j * 256 + tid, r = f >> 3, q = f & 7;
                uint2 v0, v1, v2;
                split2(xr[j].x, xr[j].y, v0.x, v1.x, v2.x);
                split2(xr[j].z, xr[j].w, v0.y, v1.y, v2.y);
                uint32_t so = (uint32_t)(r * 80 + q * 8);
                *(uint2*)(smem + dst + 0 * A_LVL + so) = v0;
                *(uint2*)(smem + dst + 1 * A_LVL + so) = v1;
                *(uint2*)(smem + dst + 2 * A_LVL + so) = v2;
            }
        }

        // ---- fold into fp32 master ----
        if ((i & (FOLD - 1)) == (FOLD - 1)) {
#pragma unroll
            for (int q = 0; q < 16; ++q) { sum[q] += acc[q]; acc[q] = 0.f; }
        }

        __syncthreads();
    }

    // ---- write logits to SMEM (aliases tile region) ----
    {
        float* lg = (float*)(smem + OFF_LOG);
#pragma unroll
        for (int mt = 0; mt < 2; ++mt) {
            int r0 = rg * 32 + mt * 16 + (lane >> 2);
#pragma unroll
            for (int nt = 0; nt < 2; ++nt) {
                int col = eg * 16 + nt * 8 + (lane & 3) * 2;
                int a0 = (mt * 2 + nt) * 4;
                float t0 = sum[a0 + 0] + acc[a0 + 0];
                float t1 = sum[a0 + 1] + acc[a0 + 1];
                float t2 = sum[a0 + 2] + acc[a0 + 2];
                float t3 = sum[a0 + 3] + acc[a0 + 3];
                *(float2*)&lg[r0 * LOGSTR + col]       = make_float2(t0, t1);
                *(float2*)&lg[(r0 + 8) * LOGSTR + col] = make_float2(t2, t3);
            }
        }
    }
    __syncthreads();

    // ---- per-row epilogue: bias + gate + top-8 + masked softmax ----
    if (tid < CTAROWS) {
        const float* lg = (const float*)(smem + OFF_LOG) + tid * LOGSTR;
        const float* bs = (const float*)(smem + OFF_BIAS);
        float v[EXP];
#pragma unroll
        for (int c = 0; c < EXP; ++c) v[c] = lg[c] + bs[c];

        const long long grow = row_base + tid;
        float* gr = gate + grow * EXP;
#pragma unroll
        for (int c = 0; c < 16; ++c)
            ((float4*)gr)[c] = make_float4(v[4*c], v[4*c+1], v[4*c+2], v[4*c+3]);

        unsigned long long mask = 0ull;
        float sval[TOPK]; int sidx[TOPK];
        for (int t = 0; t < TOPK; ++t) {
            float best = -INFINITY; int bi = 0;
#pragma unroll
            for (int c = 0; c < EXP; ++c) {
                bool fr = !((mask >> c) & 1ull);
                if (fr && v[c] > best) { best = v[c]; bi = c; }   // tie -> lower idx
            }
            mask |= 1ull << bi;
            sval[t] = best; sidx[t] = bi;
        }
        float mx = sval[0], sumv = 0.f;
#pragma unroll
        for (int t = 0; t < TOPK; ++t) sumv += expf(sval[t] - mx);
        float inv = 1.0f / sumv;

        float* sr = sparse + grow * EXP;
#pragma unroll
        for (int c = 0; c < EXP; ++c) sr[c] = 0.0f;
        for (int t = 0; t < TOPK; ++t) {
            sr[sidx[t]] = expf(sval[t] - mx) * inv;
            idxf[grow * TOPK + t] = (float)sidx[t];
        }
    }
}

extern "C" void kernel_launch(void* const* d_in, const int* in_sizes, int n_in,
                              void* d_out, int out_size)
{
    const float* x = (const float*)d_in[0];
    const float* W = (const float*)d_in[1];
    const float* b = (const float*)d_in[2];

    const int M = in_sizes[0] / HDIM;     // 16384

    float* out    = (float*)d_out;
    float* sparse = out;
    float* idxf   = out + (long long)M * EXP;
    float* gate   = out + (long long)M * EXP + (long long)M * TOPK;

    wfrag_kernel<<<(NFRAG + 255) / 256, 256>>>(W);
    gating_fused<<<M / CTAROWS, THREADS, SMEM_SZ>>>(x, b, sparse, idxf, gate);
}

// round 9
// speedup vs baseline: 1.8256x; 1.0023x over previous
#include <cuda_runtime.h>
#include <cuda_bf16.h>
#include <math.h>
#include <stdint.h>

#define HDIM    4096
#define EXP     64
#define TOPK    8
#define CTAROWS 64
#define THREADS 256
#define KC      32
#define NCHUNK  (HDIM / KC)      // 128
#define FOLD    4

// SMEM: double-buffered A tiles (bf16x3, 64 rows x 32k, 80B stride) + bias.
#define OFF_BIAS 0
#define OFF_A    256
#define A_LVL    (CTAROWS * 80)          // 5120
#define A_STG    (3 * A_LVL)             // 15360
#define SMEM_SZ  (OFF_A + 2 * A_STG)     // 30976
#define OFF_LOG  OFF_A                   // 64*66*4 = 16896 fits
#define LOGSTR   66

// W in B-fragment order: [chunk][ks][lvb][nt(8)][lane(32)] -> uint2{b0,b1}
#define NFRAG (NCHUNK * 2 * 3 * 8 * 32)
__device__ uint2 g_wfrag[NFRAG];

// ---------------- helpers ----------------
static __device__ __forceinline__ uint32_t smem_u32(const void* p) {
    uint32_t a;
    asm("{ .reg .u64 t; cvta.to.shared.u64 t, %1; cvt.u32.u64 %0, t; }"
        : "=r"(a) : "l"(p));
    return a;
}
static __device__ __forceinline__ void split2(float a0, float a1,
                                              uint32_t& u0, uint32_t& u1, uint32_t& u2) {
    __nv_bfloat162 h0 = __floats2bfloat162_rn(a0, a1);
    float r0 = a0 - __bfloat162float(h0.x);
    float r1 = a1 - __bfloat162float(h0.y);
    __nv_bfloat162 h1 = __floats2bfloat162_rn(r0, r1);
    float s0 = r0 - __bfloat162float(h1.x);
    float s1 = r1 - __bfloat162float(h1.y);
    __nv_bfloat162 h2 = __floats2bfloat162_rn(s0, s1);
    u0 = reinterpret_cast<uint32_t&>(h0);
    u1 = reinterpret_cast<uint32_t&>(h1);
    u2 = reinterpret_cast<uint32_t&>(h2);
}
static __device__ __forceinline__ void ldsm4(uint32_t* r, uint32_t addr) {
    asm volatile("ldmatrix.sync.aligned.m8n8.x4.shared.b16 {%0,%1,%2,%3}, [%4];"
                 : "=r"(r[0]), "=r"(r[1]), "=r"(r[2]), "=r"(r[3]) : "r"(addr));
}
static __device__ __forceinline__ void mma16816(float* c, const uint32_t* a,
                                                const uint32_t* b) {
    asm volatile(
        "mma.sync.aligned.m16n8k16.row.col.f32.bf16.bf16.f32 "
        "{%0,%1,%2,%3}, {%4,%5,%6,%7}, {%8,%9}, {%0,%1,%2,%3};"
        : "+f"(c[0]), "+f"(c[1]), "+f"(c[2]), "+f"(c[3])
        : "r"(a[0]), "r"(a[1]), "r"(a[2]), "r"(a[3]), "r"(b[0]), "r"(b[1]));
}

// ---------------- W repack: fp32 -> bf16x3 B-fragments ----------------
__global__ void wfrag_kernel(const float* __restrict__ W) {
    int idx = blockIdx.x * blockDim.x + threadIdx.x;
    if (idx >= NFRAG) return;
    int lane = idx & 31;
    int nt   = (idx >> 5) & 7;
    int t    = idx >> 8;
    int lvb  = t % 3; t /= 3;
    int ks   = t & 1;
    int ch   = t >> 1;
    int e = nt * 8 + (lane >> 2);
    int k = ch * KC + ks * 16 + (lane & 3) * 2;
    const float* w = W + (long long)e * HDIM + k;
    uint32_t u0a, u1a, u2a, u0b, u1b, u2b;
    split2(w[0], w[1], u0a, u1a, u2a);
    split2(w[8], w[9], u0b, u1b, u2b);
    uint2 v;
    v.x = (lvb == 0) ? u0a : (lvb == 1) ? u1a : u2a;
    v.y = (lvb == 0) ? u0b : (lvb == 1) ? u1b : u2b;
    g_wfrag[idx] = v;
}

// ---------------- fused gating ----------------
__global__ __launch_bounds__(THREADS, 2)
void gating_fused(const float* __restrict__ x, const float* __restrict__ b,
                  float* __restrict__ sparse, float* __restrict__ idxf,
                  float* __restrict__ gate)
{
    extern __shared__ char smem[];
    const uint32_t sb = smem_u32(smem);
    const int tid  = threadIdx.x;
    const int warp = tid >> 5;
    const int lane = tid & 31;
    const int rg = warp & 1;      // rows rg*32..+32
    const int eg = warp >> 1;     // experts eg*16..+16 (nt tiles 2eg, 2eg+1)
    const long long row_base = (long long)blockIdx.x * CTAROWS;

    if (tid < EXP) ((float*)(smem + OFF_BIAS))[tid] = b[tid];

    const float4* __restrict__ x4 = reinterpret_cast<const float4*>(x);

    const uint32_t a_lane = (uint32_t)((lane & 15) * 80 + (lane >> 4) * 16);
    const uint32_t a_base = sb + OFF_A + (uint32_t)rg * (32 * 80) + a_lane;

    float acc[16], sum[16];
#pragma unroll
    for (int i = 0; i < 16; ++i) { acc[i] = 0.f; sum[i] = 0.f; }

    // ---- prologue: load + convert chunk 0 into stage 0 ----
    float4 xr[2];
#pragma unroll
    for (int j = 0; j < 2; ++j) {
        int f = j * 256 + tid, r = f >> 3, q = f & 7;
        xr[j] = x4[(row_base + r) * (HDIM / 4) + q];
    }
#pragma unroll
    for (int j = 0; j < 2; ++j) {
        int f = j * 256 + tid, r = f >> 3, q = f & 7;
        uint2 v0, v1, v2;
        split2(xr[j].x, xr[j].y, v0.x, v1.x, v2.x);
        split2(xr[j].z, xr[j].w, v0.y, v1.y, v2.y);
        uint32_t so = (uint32_t)(r * 80 + q * 8);
        *(uint2*)(smem + OFF_A + 0 * A_LVL + so) = v0;
        *(uint2*)(smem + OFF_A + 1 * A_LVL + so) = v1;
        *(uint2*)(smem + OFF_A + 2 * A_LVL + so) = v2;
    }

    // B fragment double buffer; preload stage (chunk0, ks0, lvb0)
    uint2 bf[2][2];
    {
        const uint2* p0 = g_wfrag + (long long)(eg * 2) * 32 + lane;
        bf[0][0] = p0[0];
        bf[0][1] = p0[32];
    }
    int pp = 0;

    __syncthreads();

    for (int i = 0; i < NCHUNK; ++i) {
        const int stg = i & 1;
        const uint32_t a_st = a_base + (uint32_t)stg * A_STG;

        // ---- prefetch x for chunk i+1 ----
        if (i + 1 < NCHUNK) {
#pragma unroll
            for (int j = 0; j < 2; ++j) {
                int f = j * 256 + tid, r = f >> 3, q = f & 7;
                xr[j] = x4[(row_base + r) * (HDIM / 4) + (i + 1) * 8 + q];
            }
        }

        // ---- compute from stage stg; B frags via pipelined LDG ----
#pragma unroll
        for (int ks = 0; ks < 2; ++ks) {
            uint32_t afr[3][2][4];
#pragma unroll
            for (int lv = 0; lv < 3; ++lv)
#pragma unroll
                for (int mt = 0; mt < 2; ++mt)
                    ldsm4(afr[lv][mt], a_st + lv * A_LVL + mt * (16 * 80) + ks * 32);

#pragma unroll
            for (int lvb = 0; lvb < 3; ++lvb) {
                int nks = ks, nlvb = lvb + 1, nch = i;
                if (nlvb == 3) {
                    nlvb = 0; nks = ks + 1;
                    if (nks == 2) { nks = 0; nch = (i + 1 < NCHUNK) ? i + 1 : i; }
                }
                const uint2* np = g_wfrag +
                    ((long long)(((nch * 2 + nks) * 3 + nlvb) * 8 + eg * 2) * 32) + lane;
                bf[pp ^ 1][0] = np[0];
                bf[pp ^ 1][1] = np[32];

                const int na = 3 - lvb;
#pragma unroll
                for (int ap = 0; ap < 3; ++ap) {
                    if (ap < na) {
#pragma unroll
                        for (int mt = 0; mt < 2; ++mt)
#pragma unroll
                            for (int nt = 0; nt < 2; ++nt)
                                mma16816(&acc[(mt * 2 + nt) * 4], afr[ap][mt],
                                         (const uint32_t*)&bf[pp][nt]);
                    }
                }
                pp ^= 1;
            }
        }

        // ---- convert chunk i+1 into the other stage ----
        if (i + 1 < NCHUNK) {
            const uint32_t dst = OFF_A + (uint32_t)(stg ^ 1) * A_STG;
#pragma unroll
            for (int j = 0; j < 2; ++j) {
                int f = j * 256 + tid, r = f >> 3, q = f & 7;
                uint2 v0, v1, v2;
                split2(xr[j].x, xr[j].y, v0.x, v1.x, v2.x);
                split2(xr[j].z, xr[j].w, v0.y, v1.y, v2.y);
                uint32_t so = (uint32_t)(r * 80 + q * 8);
                *(uint2*)(smem + dst + 0 * A_LVL + so) = v0;
                *(uint2*)(smem + dst + 1 * A_LVL + so) = v1;
                *(uint2*)(smem + dst + 2 * A_LVL + so) = v2;
            }
        }

        // ---- fold into fp32 master ----
        if ((i & (FOLD - 1)) == (FOLD - 1)) {
#pragma unroll
            for (int q = 0; q < 16; ++q) { sum[q] += acc[q]; acc[q] = 0.f; }
        }

        __syncthreads();
    }

    // ---- write logits to SMEM (aliases tile region) ----
    {
        float* lg = (float*)(smem + OFF_LOG);
#pragma unroll
        for (int mt = 0; mt < 2; ++mt) {
            int r0 = rg * 32 + mt * 16 + (lane >> 2);
#pragma unroll
            for (int nt = 0; nt < 2; ++nt) {
                int col = eg * 16 + nt * 8 + (lane & 3) * 2;
                int a0 = (mt * 2 + nt) * 4;
                float t0 = sum[a0 + 0] + acc[a0 + 0];
                float t1 = sum[a0 + 1] + acc[a0 + 1];
                float t2 = sum[a0 + 2] + acc[a0 + 2];
                float t3 = sum[a0 + 3] + acc[a0 + 3];
                *(float2*)&lg[r0 * LOGSTR + col]       = make_float2(t0, t1);
                *(float2*)&lg[(r0 + 8) * LOGSTR + col] = make_float2(t2, t3);
            }
        }
    }
    __syncthreads();

    // ---- per-row epilogue: bias + gate + top-8 + masked softmax ----
    if (tid < CTAROWS) {
        const float* lg = (const float*)(smem + OFF_LOG) + tid * LOGSTR;
        const float* bs = (const float*)(smem + OFF_BIAS);
        float v[EXP];
#pragma unroll
        for (int c = 0; c < EXP; ++c) v[c] = lg[c] + bs[c];

        const long long grow = row_base + tid;
        float* gr = gate + grow * EXP;
#pragma unroll
        for (int c = 0; c < 16; ++c)
            ((float4*)gr)[c] = make_float4(v[4*c], v[4*c+1], v[4*c+2], v[4*c+3]);

        unsigned long long mask = 0ull;
        float sval[TOPK]; int sidx[TOPK];
        for (int t = 0; t < TOPK; ++t) {
            float best = -INFINITY; int bi = 0;
#pragma unroll
            for (int c = 0; c < EXP; ++c) {
                bool fr = !((mask >> c) & 1ull);
                if (fr && v[c] > best) { best = v[c]; bi = c; }   // tie -> lower idx
            }
            mask |= 1ull << bi;
            sval[t] = best; sidx[t] = bi;
        }
        float mx = sval[0], sumv = 0.f;
#pragma unroll
        for (int t = 0; t < TOPK; ++t) sumv += expf(sval[t] - mx);
        float inv = 1.0f / sumv;

        float* sr = sparse + grow * EXP;
#pragma unroll
        for (int c = 0; c < EXP; ++c) sr[c] = 0.0f;
        for (int t = 0; t < TOPK; ++t) {
            sr[sidx[t]] = expf(sval[t] - mx) * inv;
            idxf[grow * TOPK + t] = (float)sidx[t];
        }
    }
}

extern "C" void kernel_launch(void* const* d_in, const int* in_sizes, int n_in,
                              void* d_out, int out_size)
{
    const float* x = (const float*)d_in[0];
    const float* W = (const float*)d_in[1];
    const float* b = (const float*)d_in[2];

    const int M = in_sizes[0] / HDIM;     // 16384

    float* out    = (float*)d_out;
    float* sparse = out;
    float* idxf   = out + (long long)M * EXP;
    float* gate   = out + (long long)M * EXP + (long long)M * TOPK;

    wfrag_kernel<<<(NFRAG + 255) / 256, 256>>>(W);
    gating_fused<<<M / CTAROWS, THREADS, SMEM_SZ>>>(x, b, sparse, idxf, gate);
}

// round 10
// speedup vs baseline: 2.4001x; 1.3147x over previous
#include <cuda_runtime.h>
#include <cuda_fp16.h>
#include <math.h>
#include <stdint.h>

#define HDIM    4096
#define EXP     64
#define TOPK    8
#define CTAROWS 64
#define THREADS 256
#define KC      32
#define NCHUNK  (HDIM / KC)      // 128
#define FOLD    4
#define WSCALE  64.0f
#define WINV    (1.0f / 64.0f)

// SMEM: double-buffered A tiles (fp16x2, 64 rows x 32k, 80B stride) + bias.
#define OFF_BIAS 0
#define OFF_A    256
#define A_LVL    (CTAROWS * 80)          // 5120
#define A_STG    (2 * A_LVL)             // 10240
#define SMEM_SZ  (OFF_A + 2 * A_STG)     // 20736
#define OFF_LOG  OFF_A                   // 64*66*4 = 16896 fits in 20480
#define LOGSTR   66

// W (x64) in B-fragment order: [chunk][ks][lvb(2)][nt(8)][lane(32)] -> uint2{b0,b1}
#define NFRAG (NCHUNK * 2 * 2 * 8 * 32)
__device__ uint2 g_wfrag[NFRAG];

// ---------------- helpers ----------------
static __device__ __forceinline__ uint32_t smem_u32(const void* p) {
    uint32_t a;
    asm("{ .reg .u64 t; cvta.to.shared.u64 t, %1; cvt.u32.u64 %0, t; }"
        : "=r"(a) : "l"(p));
    return a;
}
// split fp32 pair -> 2 packed fp16x2 words (a ~= h0 + h1, residual ~2^-22)
static __device__ __forceinline__ void split2h(float a0, float a1,
                                               uint32_t& u0, uint32_t& u1) {
    __half h0x = __float2half_rn(a0), h0y = __float2half_rn(a1);
    float r0 = a0 - __half2float(h0x);
    float r1 = a1 - __half2float(h0y);
    __half h1x = __float2half_rn(r0), h1y = __float2half_rn(r1);
    __half2 p0 = __halves2half2(h0x, h0y);
    __half2 p1 = __halves2half2(h1x, h1y);
    u0 = *reinterpret_cast<uint32_t*>(&p0);
    u1 = *reinterpret_cast<uint32_t*>(&p1);
}
static __device__ __forceinline__ void ldsm4(uint32_t* r, uint32_t addr) {
    asm volatile("ldmatrix.sync.aligned.m8n8.x4.shared.b16 {%0,%1,%2,%3}, [%4];"
                 : "=r"(r[0]), "=r"(r[1]), "=r"(r[2]), "=r"(r[3]) : "r"(addr));
}
static __device__ __forceinline__ void mma16816(float* c, const uint32_t* a,
                                                const uint32_t* b) {
    asm volatile(
        "mma.sync.aligned.m16n8k16.row.col.f32.f16.f16.f32 "
        "{%0,%1,%2,%3}, {%4,%5,%6,%7}, {%8,%9}, {%0,%1,%2,%3};"
        : "+f"(c[0]), "+f"(c[1]), "+f"(c[2]), "+f"(c[3])
        : "r"(a[0]), "r"(a[1]), "r"(a[2]), "r"(a[3]), "r"(b[0]), "r"(b[1]));
}

// ---------------- W repack: fp32*64 -> fp16x2 B-fragments ----------------
__global__ void wfrag_kernel(const float* __restrict__ W) {
    int idx = blockIdx.x * blockDim.x + threadIdx.x;
    if (idx >= NFRAG) return;
    int lane = idx & 31;
    int nt   = (idx >> 5) & 7;
    int t    = idx >> 8;
    int lvb  = t & 1;
    int ks   = (t >> 1) & 1;
    int ch   = t >> 2;
    int e = nt * 8 + (lane >> 2);
    int k = ch * KC + ks * 16 + (lane & 3) * 2;
    const float* w = W + (long long)e * HDIM + k;
    uint32_t u0a, u1a, u0b, u1b;
    split2h(w[0] * WSCALE, w[1] * WSCALE, u0a, u1a);
    split2h(w[8] * WSCALE, w[9] * WSCALE, u0b, u1b);
    uint2 v;
    v.x = lvb ? u1a : u0a;
    v.y = lvb ? u1b : u0b;
    g_wfrag[idx] = v;
}

// ---------------- fused gating ----------------
__global__ __launch_bounds__(THREADS, 2)
void gating_fused(const float* __restrict__ x, const float* __restrict__ b,
                  float* __restrict__ sparse, float* __restrict__ idxf,
                  float* __restrict__ gate)
{
    extern __shared__ char smem[];
    const uint32_t sb = smem_u32(smem);
    const int tid  = threadIdx.x;
    const int warp = tid >> 5;
    const int lane = tid & 31;
    const int rg = warp & 1;      // rows rg*32..+32
    const int eg = warp >> 1;     // experts eg*16..+16 (nt tiles 2eg, 2eg+1)
    const long long row_base = (long long)blockIdx.x * CTAROWS;

    if (tid < EXP) ((float*)(smem + OFF_BIAS))[tid] = b[tid];

    const float4* __restrict__ x4 = reinterpret_cast<const float4*>(x);

    const uint32_t a_lane = (uint32_t)((lane & 15) * 80 + (lane >> 4) * 16);
    const uint32_t a_base = sb + OFF_A + (uint32_t)rg * (32 * 80) + a_lane;

    float acc[16], sum[16];
#pragma unroll
    for (int i = 0; i < 16; ++i) { acc[i] = 0.f; sum[i] = 0.f; }

    // ---- prologue: load + convert chunk 0 into stage 0 ----
    float4 xr[2];
#pragma unroll
    for (int j = 0; j < 2; ++j) {
        int f = j * 256 + tid, r = f >> 3, q = f & 7;
        xr[j] = x4[(row_base + r) * (HDIM / 4) + q];
    }
#pragma unroll
    for (int j = 0; j < 2; ++j) {
        int f = j * 256 + tid, r = f >> 3, q = f & 7;
        uint2 v0, v1;
        split2h(xr[j].x, xr[j].y, v0.x, v1.x);
        split2h(xr[j].z, xr[j].w, v0.y, v1.y);
        uint32_t so = (uint32_t)(r * 80 + q * 8);
        *(uint2*)(smem + OFF_A + 0 * A_LVL + so) = v0;
        *(uint2*)(smem + OFF_A + 1 * A_LVL + so) = v1;
    }

    // B fragment double buffer; preload (chunk0, ks0, lvb0)
    uint2 bf[2][2];
    {
        const uint2* p0 = g_wfrag + (long long)(eg * 2) * 32 + lane;
        bf[0][0] = p0[0];
        bf[0][1] = p0[32];
    }
    int pp = 0;

    __syncthreads();

    for (int i = 0; i < NCHUNK; ++i) {
        const int stg = i & 1;
        const uint32_t a_st = a_base + (uint32_t)stg * A_STG;

        // ---- prefetch x for chunk i+1 ----
        if (i + 1 < NCHUNK) {
#pragma unroll
            for (int j = 0; j < 2; ++j) {
                int f = j * 256 + tid, r = f >> 3, q = f & 7;
                xr[j] = x4[(row_base + r) * (HDIM / 4) + (i + 1) * 8 + q];
            }
        }

        // ---- compute: per ks, 3 passes (b0c0, b1c0, b0c1) ----
#pragma unroll
        for (int ks = 0; ks < 2; ++ks) {
            uint32_t afr[2][2][4];
#pragma unroll
            for (int lv = 0; lv < 2; ++lv)
#pragma unroll
                for (int mt = 0; mt < 2; ++mt)
                    ldsm4(afr[lv][mt], a_st + lv * A_LVL + mt * (16 * 80) + ks * 32);

            // prefetch (i, ks, lvb=1)
            {
                const uint2* np = g_wfrag +
                    ((long long)(((i * 2 + ks) * 2 + 1) * 8 + eg * 2) * 32) + lane;
                bf[pp ^ 1][0] = np[0];
                bf[pp ^ 1][1] = np[32];
            }
            // passes with B level 0: A levels 0 and 1 (b0c0 + b1c0)
#pragma unroll
            for (int ap = 0; ap < 2; ++ap)
#pragma unroll
                for (int mt = 0; mt < 2; ++mt)
#pragma unroll
                    for (int nt = 0; nt < 2; ++nt)
                        mma16816(&acc[(mt * 2 + nt) * 4], afr[ap][mt],
                                 (const uint32_t*)&bf[pp][nt]);
            pp ^= 1;

            // prefetch next stage's lvb0: (i, ks+1) or (i+1, 0)
            {
                int nch = i, nks = ks + 1;
                if (nks == 2) { nks = 0; nch = (i + 1 < NCHUNK) ? i + 1 : i; }
                const uint2* np = g_wfrag +
                    ((long long)(((nch * 2 + nks) * 2 + 0) * 8 + eg * 2) * 32) + lane;
                bf[pp ^ 1][0] = np[0];
                bf[pp ^ 1][1] = np[32];
            }
            // pass with B level 1: A level 0 (b0c1)
#pragma unroll
            for (int mt = 0; mt < 2; ++mt)
#pragma unroll
                for (int nt = 0; nt < 2; ++nt)
                    mma16816(&acc[(mt * 2 + nt) * 4], afr[0][mt],
                             (const uint32_t*)&bf[pp][nt]);
            pp ^= 1;
        }

        // ---- convert chunk i+1 into the other stage ----
        if (i + 1 < NCHUNK) {
            const uint32_t dst = OFF_A + (uint32_t)(stg ^ 1) * A_STG;
#pragma unroll
            for (int j = 0; j < 2; ++j) {
                int f = j * 256 + tid, r = f >> 3, q = f & 7;
                uint2 v0, v1;
                split2h(xr[j].x, xr[j].y, v0.x, v1.x);
                split2h(xr[j].z, xr[j].w, v0.y, v1.y);
                uint32_t so = (uint32_t)(r * 80 + q * 8);
                *(uint2*)(smem + dst + 0 * A_LVL + so) = v0;
                *(uint2*)(smem + dst + 1 * A_LVL + so) = v1;
            }
        }

        // ---- fold into fp32 master (bounds HMMA chain bias) ----
        if ((i & (FOLD - 1)) == (FOLD - 1)) {
#pragma unroll
            for (int q = 0; q < 16; ++q) { sum[q] += acc[q]; acc[q] = 0.f; }
        }

        __syncthreads();
    }

    // ---- write logits to SMEM (undo W scale) ----
    {
        float* lg = (float*)(smem + OFF_LOG);
#pragma unroll
        for (int mt = 0; mt < 2; ++mt) {
            int r0 = rg * 32 + mt * 16 + (lane >> 2);
#pragma unroll
            for (int nt = 0; nt < 2; ++nt) {
                int col = eg * 16 + nt * 8 + (lane & 3) * 2;
                int a0 = (mt * 2 + nt) * 4;
                float t0 = (sum[a0 + 0] + acc[a0 + 0]) * WINV;
                float t1 = (sum[a0 + 1] + acc[a0 + 1]) * WINV;
                float t2 = (sum[a0 + 2] + acc[a0 + 2]) * WINV;
                float t3 = (sum[a0 + 3] + acc[a0 + 3]) * WINV;
                *(float2*)&lg[r0 * LOGSTR + col]       = make_float2(t0, t1);
                *(float2*)&lg[(r0 + 8) * LOGSTR + col] = make_float2(t2, t3);
            }
        }
    }
    __syncthreads();

    // ---- per-row epilogue: bias + gate + top-8 + masked softmax ----
    if (tid < CTAROWS) {
        const float* lg = (const float*)(smem + OFF_LOG) + tid * LOGSTR;
        const float* bs = (const float*)(smem + OFF_BIAS);
        float v[EXP];
#pragma unroll
        for (int c = 0; c < EXP; ++c) v[c] = lg[c] + bs[c];

        const long long grow = row_base + tid;
        float* gr = gate + grow * EXP;
#pragma unroll
        for (int c = 0; c < 16; ++c)
            ((float4*)gr)[c] = make_float4(v[4*c], v[4*c+1], v[4*c+2], v[4*c+3]);

        unsigned long long mask = 0ull;
        float sval[TOPK]; int sidx[TOPK];
        for (int t = 0; t < TOPK; ++t) {
            float best = -INFINITY; int bi = 0;
#pragma unroll
            for (int c = 0; c < EXP; ++c) {
                bool fr = !((mask >> c) & 1ull);
                if (fr && v[c] > best) { best = v[c]; bi = c; }   // tie -> lower idx
            }
            mask |= 1ull << bi;
            sval[t] = best; sidx[t] = bi;
        }
        float mx = sval[0], sumv = 0.f;
#pragma unroll
        for (int t = 0; t < TOPK; ++t) sumv += expf(sval[t] - mx);
        float inv = 1.0f / sumv;

        float* sr = sparse + grow * EXP;
#pragma unroll
        for (int c = 0; c < EXP; ++c) sr[c] = 0.0f;
        for (int t = 0; t < TOPK; ++t) {
            sr[sidx[t]] = expf(sval[t] - mx) * inv;
            idxf[grow * TOPK + t] = (float)sidx[t];
        }
    }
}

extern "C" void kernel_launch(void* const* d_in, const int* in_sizes, int n_in,
                              void* d_out, int out_size)
{
    const float* x = (const float*)d_in[0];
    const float* W = (const float*)d_in[1];
    const float* b = (const float*)d_in[2];

    const int M = in_sizes[0] / HDIM;     // 16384

    float* out    = (float*)d_out;
    float* sparse = out;
    float* idxf   = out + (long long)M * EXP;
    float* gate   = out + (long long)M * EXP + (long long)M * TOPK;

    wfrag_kernel<<<(NFRAG + 255) / 256, 256>>>(W);
    gating_fused<<<M / CTAROWS, THREADS, SMEM_SZ>>>(x, b, sparse, idxf, gate);
}